// round 16
// baseline (speedup 1.0000x reference)
#include <cuda_runtime.h>
#include <cuda_bf16.h>
#include <math.h>
#include <stdint.h>

#define BB 256
#define SS 512
#define II 256
#define HH 256
#define OO 256
#define LL 64

__device__ float g_xproj[(size_t)SS * BB * HH];
__device__ float g_ahist[(size_t)BB * LL * HH];
__device__ __nv_bfloat16 g_wh[256 * 256];
__device__ __nv_bfloat16 g_wl[256 * 256];
__device__ __nv_bfloat16 g_wyh[256 * 256];
__device__ __nv_bfloat16 g_wyl[256 * 256];

__device__ __forceinline__ float sigf(float x) {
    return __fdividef(1.f, 1.f + __expf(-x));
}
__device__ __forceinline__ float tanhfast(float x) {
    float e = __expf(2.f * x);
    return 1.f - __fdividef(2.f, e + 1.f);
}

__device__ __forceinline__ uint32_t smem_u32(const void* p) {
    uint32_t r;
    asm("{ .reg .u64 t; cvta.to.shared.u64 t, %1; cvt.u32.u64 %0, t; }" : "=r"(r) : "l"(p));
    return r;
}
__device__ __forceinline__ uint32_t mapa_peer(uint32_t a, uint32_t peer) {
    uint32_t r;
    asm("mapa.shared::cluster.u32 %0, %1, %2;" : "=r"(r) : "r"(a), "r"(peer));
    return r;
}
__device__ __forceinline__ void mbar_init(uint32_t a, uint32_t c) {
    asm volatile("mbarrier.init.shared.b64 [%0], %1;" :: "r"(a), "r"(c) : "memory");
}
__device__ __forceinline__ void mbar_arrive_local(uint32_t a) {
    asm volatile("mbarrier.arrive.release.cta.shared::cta.b64 _, [%0];"
                 :: "r"(a) : "memory");
}
__device__ __forceinline__ void mbar_arrive_cluster(uint32_t a) {
    asm volatile("mbarrier.arrive.release.cluster.shared::cluster.b64 _, [%0];"
                 :: "r"(a) : "memory");
}
__device__ __forceinline__ void mbar_wait_par(uint32_t a, uint32_t par) {
    asm volatile(
        "{\n\t.reg .pred P;\n\t"
        "WL%=:\n\t"
        "mbarrier.try_wait.parity.acquire.cluster.shared::cta.b64 P, [%0], %1, 0x989680;\n\t"
        "@P bra WD%=;\n\t"
        "bra WL%=;\n\t"
        "WD%=:\n\t}"
        :: "r"(a), "r"(par) : "memory");
}
__device__ __forceinline__ void st_cluster_f4(uint32_t a, float4 v) {
    asm volatile("st.shared::cluster.v4.b32 [%0], {%1,%2,%3,%4};" :: "r"(a),
                 "r"(__float_as_uint(v.x)), "r"(__float_as_uint(v.y)),
                 "r"(__float_as_uint(v.z)), "r"(__float_as_uint(v.w)) : "memory");
}
__device__ __forceinline__ void st_cluster_u32(uint32_t a, uint32_t v) {
    asm volatile("st.shared::cluster.b32 [%0], %1;" :: "r"(a), "r"(v) : "memory");
}
__device__ __forceinline__ void cluster_sync_all() {
    asm volatile("barrier.cluster.arrive.aligned;" ::: "memory");
    asm volatile("barrier.cluster.wait.aligned;" ::: "memory");
}
__device__ __forceinline__ void ldsm_x4(uint32_t addr, uint32_t r[4]) {
    asm volatile("ldmatrix.sync.aligned.m8n8.x4.shared.b16 {%0,%1,%2,%3}, [%4];"
                 : "=r"(r[0]), "=r"(r[1]), "=r"(r[2]), "=r"(r[3]) : "r"(addr));
}
__device__ __forceinline__ void ldsm_x4t(uint32_t addr, uint32_t& r0, uint32_t& r1,
                                         uint32_t& r2, uint32_t& r3) {
    asm volatile("ldmatrix.sync.aligned.m8n8.x4.trans.shared.b16 {%0,%1,%2,%3}, [%4];"
                 : "=r"(r0), "=r"(r1), "=r"(r2), "=r"(r3) : "r"(addr));
}
__device__ __forceinline__ void mma_bf16(float c[4], const uint32_t a[4],
                                         uint32_t b0, uint32_t b1) {
    asm volatile(
        "mma.sync.aligned.m16n8k16.row.col.f32.bf16.bf16.f32 "
        "{%0,%1,%2,%3}, {%4,%5,%6,%7}, {%8,%9}, {%0,%1,%2,%3};"
        : "+f"(c[0]), "+f"(c[1]), "+f"(c[2]), "+f"(c[3])
        : "r"(a[0]), "r"(a[1]), "r"(a[2]), "r"(a[3]), "r"(b0), "r"(b1));
}
__device__ __forceinline__ uint32_t packbf2(float a, float b) {
    __nv_bfloat16 ha = __float2bfloat16(a), hb = __float2bfloat16(b);
    return ((uint32_t)__bfloat16_as_ushort(hb) << 16) | __bfloat16_as_ushort(ha);
}
__device__ __forceinline__ float bfu(uint32_t u) {
    return __bfloat162float(__ushort_as_bfloat16((unsigned short)(u & 0xffffu)));
}

// ===========================================================================
// Kernel 0a/0b: W1x / Wy -> bf16 hi/lo, transposed to [n][k]
// ===========================================================================
__global__ void wconv_kernel(const float* __restrict__ W1x)
{
    int k = blockIdx.x, n = threadIdx.x;
    float v = W1x[k * 256 + n];
    __nv_bfloat16 h = __float2bfloat16(v);
    __nv_bfloat16 l = __float2bfloat16(v - __bfloat162float(h));
    g_wh[n * 256 + k] = h;
    g_wl[n * 256 + k] = l;
}
__global__ void wconv_wy_kernel(const float* __restrict__ Wy)
{
    int k = blockIdx.x, n = threadIdx.x;
    float v = Wy[k * 256 + n];
    __nv_bfloat16 h = __float2bfloat16(v);
    __nv_bfloat16 l = __float2bfloat16(v - __bfloat162float(h));
    g_wyh[n * 256 + k] = h;
    g_wyl[n * 256 + k] = l;
}

// ===========================================================================
// Shared GEMM pieces (R8-proven)
// ===========================================================================
#define SB_BH    0
#define SB_BL    65536
#define SB_A     131072
#define SB_BIAS  196608
#define XP_SMEM  197120

__device__ __forceinline__ void afragx(uint32_t Ab, int mbase, int j, int lane,
                                       uint32_t r[4]) {
    int row = mbase + (lane & 15);
    int q   = j * 2 + (lane >> 4);
    uint32_t addr = Ab + (uint32_t)(row * 128 + ((q ^ row) & 7) * 16);
    ldsm_x4(addr, r);
}
__device__ __forceinline__ void bfragx(uint32_t Bb, int nbase, int ks, int lane,
                                       uint32_t r[4]) {
    int row = nbase + (lane & 7) + ((lane >> 4) << 3);
    int q   = ks * 2 + ((lane >> 3) & 1);
    uint32_t qp = (uint32_t)((q & ~7) | ((q ^ row) & 7));
    uint32_t addr = Bb + (uint32_t)(row * 512) + qp * 16;
    ldsm_x4(addr, r);
}

__device__ __forceinline__ void load_a_rows(unsigned char* sm, int p,
                                            const float* __restrict__ Arows,
                                            int c, int t)
{
    const int r = t >> 1, hf = t & 1, rx = r & 7;
    unsigned char* ah = sm + SB_A + p * 32768;
    unsigned char* al = ah + 16384;
    const float* xr = Arows + (size_t)r * 256 + c * 64 + hf * 32;
    #pragma unroll
    for (int jj = 0; jj < 4; jj++) {
        float4 v0 = *(const float4*)(xr + jj * 8);
        float4 v1 = *(const float4*)(xr + jj * 8 + 4);
        uint4 h, l;
        h.x = packbf2(v0.x, v0.y); h.y = packbf2(v0.z, v0.w);
        h.z = packbf2(v1.x, v1.y); h.w = packbf2(v1.z, v1.w);
        l.x = packbf2(v0.x - bfu(h.x), v0.y - bfu(h.x >> 16));
        l.y = packbf2(v0.z - bfu(h.y), v0.w - bfu(h.y >> 16));
        l.z = packbf2(v1.x - bfu(h.z), v1.y - bfu(h.z >> 16));
        l.w = packbf2(v1.z - bfu(h.w), v1.w - bfu(h.w >> 16));
        int q = hf * 4 + jj;
        uint32_t off = (uint32_t)(r * 128 + (q ^ rx) * 16);
        *(uint4*)(ah + off) = h;
        *(uint4*)(al + off) = l;
    }
}

template <int MODE>
__device__ __forceinline__ void gemm128(const float* __restrict__ Arows, int m0,
                                        const __nv_bfloat16* __restrict__ Wth,
                                        const __nv_bfloat16* __restrict__ Wtl,
                                        const float* __restrict__ bias1,
                                        const float* __restrict__ bias2,
                                        int n0, float* __restrict__ outp)
{
    extern __shared__ __align__(1024) unsigned char sm[];
    const int t = threadIdx.x;
    const int wid = t >> 5, lane = t & 31;
    const uint32_t smb = smem_u32(sm);
    const int mw = (wid & 1) * 64;
    const int nw = (wid >> 1) * 32;

    #pragma unroll 4
    for (int i = 0; i < 16; i++) {
        int idx = i * 256 + t;
        int rr = idx >> 5, q = idx & 31;
        uint32_t qp = (uint32_t)((q & ~7) | ((q ^ rr) & 7));
        size_t src = (size_t)(n0 + rr) * 256 + q * 8;
        *(uint4*)(sm + SB_BH + rr * 512 + qp * 16) = *(const uint4*)(Wth + src);
        *(uint4*)(sm + SB_BL + rr * 512 + qp * 16) = *(const uint4*)(Wtl + src);
    }
    if (t < 128) {
        float b = bias1[n0 + t];
        if (bias2) b += bias2[n0 + t];
        ((float*)(sm + SB_BIAS))[t] = b;
    }
    load_a_rows(sm, 0, Arows, 0, t);
    __syncthreads();

    float acc[4][4][4];
    #pragma unroll
    for (int mt = 0; mt < 4; mt++)
        #pragma unroll
        for (int nt = 0; nt < 4; nt++)
            #pragma unroll
            for (int e = 0; e < 4; e++) acc[mt][nt][e] = 0.f;

    const uint32_t Bh = smb + SB_BH, Bl = smb + SB_BL;

    #pragma unroll 1
    for (int c = 0; c < 4; c++) {
        const int p = c & 1;
        if (c < 3) load_a_rows(sm, 1 - p, Arows, c + 1, t);
        const uint32_t Abh = smb + SB_A + p * 32768;
        const uint32_t Abl = Abh + 16384;
        #pragma unroll
        for (int j = 0; j < 4; j++) {
            const int ks = c * 4 + j;
            uint32_t bh[8], bl[8];
            bfragx(Bh, nw,      ks, lane, bh);
            bfragx(Bh, nw + 16, ks, lane, bh + 4);
            bfragx(Bl, nw,      ks, lane, bl);
            bfragx(Bl, nw + 16, ks, lane, bl + 4);
            #pragma unroll
            for (int mt = 0; mt < 4; mt++) {
                uint32_t ah[4], al[4];
                afragx(Abh, mw + mt * 16, j, lane, ah);
                afragx(Abl, mw + mt * 16, j, lane, al);
                #pragma unroll
                for (int nt = 0; nt < 4; nt++) {
                    mma_bf16(acc[mt][nt], ah, bh[nt * 2], bh[nt * 2 + 1]);
                    mma_bf16(acc[mt][nt], ah, bl[nt * 2], bl[nt * 2 + 1]);
                    mma_bf16(acc[mt][nt], al, bh[nt * 2], bh[nt * 2 + 1]);
                }
            }
        }
        __syncthreads();
    }

    const int g = lane >> 2, tig = lane & 3;
    const float* bias_sm = (const float*)(sm + SB_BIAS);
    #pragma unroll
    for (int mt = 0; mt < 4; mt++) {
        const int mrow = m0 + mw + mt * 16 + g;
        #pragma unroll
        for (int nt = 0; nt < 4; nt++) {
            const int nl = nw + nt * 8 + tig * 2;
            const float bz0 = bias_sm[nl], bz1 = bias_sm[nl + 1];
            float2 v0, v1;
            if (MODE == 0) {
                v0 = make_float2(acc[mt][nt][0] + bz0, acc[mt][nt][1] + bz1);
                v1 = make_float2(acc[mt][nt][2] + bz0, acc[mt][nt][3] + bz1);
            } else {
                v0 = make_float2(sigf(acc[mt][nt][0] + bz0), sigf(acc[mt][nt][1] + bz1));
                v1 = make_float2(sigf(acc[mt][nt][2] + bz0), sigf(acc[mt][nt][3] + bz1));
            }
            *(float2*)&outp[(size_t)mrow * 256 + n0 + nl] = v0;
            *(float2*)&outp[(size_t)(mrow + 8) * 256 + n0 + nl] = v1;
        }
    }
}

__global__ __launch_bounds__(256, 1) void xproj_mma_kernel(
    const float* __restrict__ x,
    const float* __restrict__ b1x, const float* __restrict__ b1a)
{
    const int m0 = blockIdx.x * 128;
    const int n0 = blockIdx.y * 128;
    const int s  = m0 >> 8;
    const int b0 = m0 & 255;
    extern __shared__ __align__(1024) unsigned char sm[];
    const int t = threadIdx.x;
    const int wid = t >> 5, lane = t & 31;
    const uint32_t smb = smem_u32(sm);
    const int mw = (wid & 1) * 64;
    const int nw = (wid >> 1) * 32;

    #pragma unroll 4
    for (int i = 0; i < 16; i++) {
        int idx = i * 256 + t;
        int rr = idx >> 5, q = idx & 31;
        uint32_t qp = (uint32_t)((q & ~7) | ((q ^ rr) & 7));
        size_t src = (size_t)(n0 + rr) * 256 + q * 8;
        *(uint4*)(sm + SB_BH + rr * 512 + qp * 16) = *(const uint4*)(g_wh + src);
        *(uint4*)(sm + SB_BL + rr * 512 + qp * 16) = *(const uint4*)(g_wl + src);
    }
    if (t < 128)
        ((float*)(sm + SB_BIAS))[t] = b1x[n0 + t] + b1a[n0 + t];

    auto load_chunk = [&](int p, int c) {
        const int r = t >> 1, hf = t & 1, rx = r & 7;
        unsigned char* ah = sm + SB_A + p * 32768;
        unsigned char* al = ah + 16384;
        const float* xr = x + ((size_t)(b0 + r) * SS + s) * II + c * 64 + hf * 32;
        #pragma unroll
        for (int jj = 0; jj < 4; jj++) {
            float4 v0 = *(const float4*)(xr + jj * 8);
            float4 v1 = *(const float4*)(xr + jj * 8 + 4);
            uint4 h, l;
            h.x = packbf2(v0.x, v0.y); h.y = packbf2(v0.z, v0.w);
            h.z = packbf2(v1.x, v1.y); h.w = packbf2(v1.z, v1.w);
            l.x = packbf2(v0.x - bfu(h.x), v0.y - bfu(h.x >> 16));
            l.y = packbf2(v0.z - bfu(h.y), v0.w - bfu(h.y >> 16));
            l.z = packbf2(v1.x - bfu(h.z), v1.y - bfu(h.z >> 16));
            l.w = packbf2(v1.z - bfu(h.w), v1.w - bfu(h.w >> 16));
            int q = hf * 4 + jj;
            uint32_t off = (uint32_t)(r * 128 + (q ^ rx) * 16);
            *(uint4*)(ah + off) = h;
            *(uint4*)(al + off) = l;
        }
    };

    load_chunk(0, 0);
    __syncthreads();

    float acc[4][4][4];
    #pragma unroll
    for (int mt = 0; mt < 4; mt++)
        #pragma unroll
        for (int nt = 0; nt < 4; nt++)
            #pragma unroll
            for (int e = 0; e < 4; e++) acc[mt][nt][e] = 0.f;

    const uint32_t Bh = smb + SB_BH, Bl = smb + SB_BL;

    #pragma unroll 1
    for (int c = 0; c < 4; c++) {
        const int p = c & 1;
        if (c < 3) load_chunk(1 - p, c + 1);
        const uint32_t Abh = smb + SB_A + p * 32768;
        const uint32_t Abl = Abh + 16384;
        #pragma unroll
        for (int j = 0; j < 4; j++) {
            const int ks = c * 4 + j;
            uint32_t bh[8], bl[8];
            bfragx(Bh, nw,      ks, lane, bh);
            bfragx(Bh, nw + 16, ks, lane, bh + 4);
            bfragx(Bl, nw,      ks, lane, bl);
            bfragx(Bl, nw + 16, ks, lane, bl + 4);
            #pragma unroll
            for (int mt = 0; mt < 4; mt++) {
                uint32_t ah[4], al[4];
                afragx(Abh, mw + mt * 16, j, lane, ah);
                afragx(Abl, mw + mt * 16, j, lane, al);
                #pragma unroll
                for (int nt = 0; nt < 4; nt++) {
                    mma_bf16(acc[mt][nt], ah, bh[nt * 2], bh[nt * 2 + 1]);
                    mma_bf16(acc[mt][nt], ah, bl[nt * 2], bl[nt * 2 + 1]);
                    mma_bf16(acc[mt][nt], al, bh[nt * 2], bh[nt * 2 + 1]);
                }
            }
        }
        __syncthreads();
    }

    const int g = lane >> 2, tig = lane & 3;
    const float* bias_sm = (const float*)(sm + SB_BIAS);
    #pragma unroll
    for (int mt = 0; mt < 4; mt++) {
        const int mrow = m0 + mw + mt * 16 + g;
        #pragma unroll
        for (int nt = 0; nt < 4; nt++) {
            const int nl = nw + nt * 8 + tig * 2;
            const float bz0 = bias_sm[nl], bz1 = bias_sm[nl + 1];
            float2 v0 = make_float2(acc[mt][nt][0] + bz0, acc[mt][nt][1] + bz1);
            float2 v1 = make_float2(acc[mt][nt][2] + bz0, acc[mt][nt][3] + bz1);
            *(float2*)&g_xproj[(size_t)mrow * HH + n0 + nl] = v0;
            *(float2*)&g_xproj[(size_t)(mrow + 8) * HH + n0 + nl] = v1;
        }
    }
}

__global__ __launch_bounds__(256, 1) void y_mma_kernel(
    const float* __restrict__ by, float* __restrict__ out)
{
    gemm128<1>(g_ahist + (size_t)blockIdx.x * 128 * 256, blockIdx.x * 128,
               g_wyh, g_wyl, by, nullptr, blockIdx.y * 128, out);
}

// ===========================================================================
// Kernel 2: RNN ring, 16 warps: k-half warp specialization.
//   w<8  : m-tile w, own k-half, never waits; combines + tanh + push.
//   w>=8 : m-tile w-8, peer k-half, waits on arrival barrier.
// ===========================================================================
#define A_STRIDE 528
#define ALO      67584
#define RING(i)  (135168 + (i) * 8192)
#define A4OFF    196608
#define Y4OFF    204800
#define REDOFF   208896
#define MBOFF    225408
#define BASEOFF  225472
#define RNN_SMEM 229568
#define RSTRIDE  1032
#define NT 512

__device__ __forceinline__ void gemv16_g(const float* __restrict__ Wp,
                                         const float4* __restrict__ a, float acc[16])
{
    #pragma unroll
    for (int j = 0; j < 16; j++) acc[j] = 0.f;
    #pragma unroll 16
    for (int k = 0; k < 32; k++) {
        float4 w  = *(const float4*)(Wp + (size_t)k * 256);
        float4 av = a[k];
        acc[0]  = fmaf(av.x, w.x, acc[0]);  acc[1]  = fmaf(av.x, w.y, acc[1]);
        acc[2]  = fmaf(av.x, w.z, acc[2]);  acc[3]  = fmaf(av.x, w.w, acc[3]);
        acc[4]  = fmaf(av.y, w.x, acc[4]);  acc[5]  = fmaf(av.y, w.y, acc[5]);
        acc[6]  = fmaf(av.y, w.z, acc[6]);  acc[7]  = fmaf(av.y, w.w, acc[7]);
        acc[8]  = fmaf(av.z, w.x, acc[8]);  acc[9]  = fmaf(av.z, w.y, acc[9]);
        acc[10] = fmaf(av.z, w.z, acc[10]); acc[11] = fmaf(av.z, w.w, acc[11]);
        acc[12] = fmaf(av.w, w.x, acc[12]); acc[13] = fmaf(av.w, w.y, acc[13]);
        acc[14] = fmaf(av.w, w.z, acc[14]); acc[15] = fmaf(av.w, w.w, acc[15]);
    }
}

__global__ __launch_bounds__(NT, 1) __cluster_dims__(2, 1, 1)
void rnn_kernel(const float* __restrict__ W1a,
                const float* __restrict__ W2x, const float* __restrict__ b2x,
                const float* __restrict__ W2a, const float* __restrict__ b2a,
                const float* __restrict__ Wy,  const float* __restrict__ by)
{
    extern __shared__ __align__(16) unsigned char dsm[];
    float4* a4s   = (float4*)(dsm + A4OFF);
    float4* y4s   = (float4*)(dsm + Y4OFF);
    float*  red   = (float*)(dsm + REDOFF);
    float*  basef = (float*)(dsm + BASEOFF);
    unsigned long long* mbars = (unsigned long long*)(dsm + MBOFF);

    const int t    = threadIdx.x;
    const int lane = t & 31;
    const int w    = t >> 5;           // 0..15
    const int wm   = w & 7;            // m-tile
    const int kh   = w >> 3;           // 0 = own half, 1 = peer half
    uint32_t rank;
    asm("mov.u32 %0, %%cluster_ctarank;" : "=r"(rank));
    const uint32_t peer = rank ^ 1;
    const int b0 = (blockIdx.x >> 1) * 4;
    const int c0 = (int)rank * 128;
    const int kb = kh ? (c0 ^ 128) : c0;
    const uint32_t smb = smem_u32(dsm);

    const int mb   = wm * 16;
    const int g    = lane >> 2;
    const int tig  = lane & 3;
    const bool act  = (tig < 2);
    const bool actc = act && (kh == 0);       // combine/push role
    const int colg = c0 + mb + g;
    const int nb   = 2 * tig;
    const uint32_t aAddrBase = smb + (uint32_t)((mb + (lane & 15)) * A_STRIDE)
                             + (uint32_t)((lane >> 4) * 16);
    const uint32_t bOff = (uint32_t)(((lane & 16) << 8) + (lane & 15) * 16);
    const uint32_t partAddr  = (uint32_t)(REDOFF + ((kh * 8 + wm) * 32 + lane) * 16);
    const uint32_t partPeerA = (uint32_t)(REDOFF + ((8 + wm) * 32 + lane) * 16);

    uint32_t eF[4], peF[4], pRG[4];
    #pragma unroll
    for (int i = 0; i < 4; i++) {
        eF[i]  = smem_u32(&mbars[i]);
        peF[i] = mapa_peer(eF[i], peer);
        pRG[i] = mapa_peer(smb + (uint32_t)RING(i), peer);
    }
    uint32_t py4 = mapa_peer(smb + Y4OFF, peer);

    if (t == 0) {
        mbar_init(eF[0], 128); mbar_init(eF[1], 128);
        mbar_init(eF[2], 128); mbar_init(eF[3], 128);
    }
    // zero ring slot 3 (8 KB, 512 threads x 16B)
    *(uint4*)(dsm + RING(3) + t * 16) = make_uint4(0, 0, 0, 0);
    // stage A = W1a^T hi/lo (512 threads)
    {
        const int m = t & 127, hb = t >> 7;     // hb 0..3
        #pragma unroll 4
        for (int kk = 0; kk < 64; kk++) {
            int k = hb * 64 + kk;
            float v = W1a[(size_t)k * 256 + c0 + m];
            __nv_bfloat16 h = __float2bfloat16(v);
            __nv_bfloat16 l = __float2bfloat16(v - __bfloat162float(h));
            *(unsigned short*)(dsm + m * A_STRIDE + k * 2) = __bfloat16_as_ushort(h);
            *(unsigned short*)(dsm + ALO + m * A_STRIDE + k * 2) = __bfloat16_as_ushort(l);
        }
    }
    __syncthreads();

    // register-resident weight fragments for THIS warp's k-half (64 regs)
    uint32_t ah_r[32], al_r[32];
    auto load_a_regs = [&]() {
        #pragma unroll
        for (int j = 0; j < 8; j++) {
            uint32_t aa = aAddrBase + (uint32_t)((kb + j * 16) * 2);
            ldsm_x4(aa, &ah_r[j * 4]);
            ldsm_x4(aa + ALO, &al_r[j * 4]);
        }
    };
    load_a_regs();

    cluster_sync_all();
    if (actc) mbar_arrive_local(eF[3]);     // prime slot 3 (128 arrives)

    float xc00 = 0.f, xc01 = 0.f, xc10 = 0.f, xc11 = 0.f;
    if (actc) {
        const float* xb = g_xproj + (size_t)(b0 + nb) * HH;
        xc00 = __ldcs(xb + colg);
        xc01 = __ldcs(xb + (size_t)HH + colg);
        xc10 = __ldcs(xb + colg + 8);
        xc11 = __ldcs(xb + (size_t)HH + colg + 8);
    }

    int fp0 = 0, fp1 = 0, fp2 = 0, fp3 = 0;

    // per-warp half-gemv: 8 j-iters, 24 mma; kh=1 warps wait first.
    auto ring_mma = [&](uint32_t eFr, int& fpr, uint32_t bsr, bool skipwait,
                        float sums[4]) {
        if (kh && !skipwait) { mbar_wait_par(eFr, fpr); }
        if (!skipwait) fpr ^= 1;
        float acc[6][4];
        #pragma unroll
        for (int i = 0; i < 6; i++)
            #pragma unroll
            for (int e = 0; e < 4; e++) acc[i][e] = 0.f;
        const uint32_t Bsr = smb + bsr + bOff;
        #pragma unroll
        for (int j = 0; j < 8; j++) {
            uint32_t b0r, b1r, b2r, b3r;
            ldsm_x4t(Bsr + (uint32_t)((kb + j * 16) * 16), b0r, b1r, b2r, b3r);
            const int sel = j & 1;
            mma_bf16(acc[sel],     &ah_r[j * 4], b0r, b1r);
            mma_bf16(acc[2 + sel], &ah_r[j * 4], b2r, b3r);
            mma_bf16(acc[4 + sel], &al_r[j * 4], b0r, b1r);
        }
        #pragma unroll
        for (int e = 0; e < 4; e++)
            sums[e] = acc[0][e] + acc[1][e] + acc[2][e] + acc[3][e]
                    + acc[4][e] + acc[5][e];
    };

    auto push_state = [&](uint32_t bsw, uint32_t pbsw, uint32_t pefw,
                          float t00, float t01, float t10, float t11) {
        uint32_t hA = packbf2(t00, t01);
        uint32_t hB = packbf2(t10, t11);
        uint32_t lA = packbf2(t00 - bfu(hA), t01 - bfu(hA >> 16));
        uint32_t lB = packbf2(t10 - bfu(hB), t11 - bfu(hB >> 16));
        const uint32_t o1 = (uint32_t)(colg * 16 + tig * 4);
        const uint32_t o2 = (uint32_t)((colg + 8) * 16 + tig * 4);
        *(uint32_t*)(dsm + bsw + o1) = hA;
        *(uint32_t*)(dsm + bsw + o2) = hB;
        *(uint32_t*)(dsm + bsw + 4096 + o1) = lA;
        *(uint32_t*)(dsm + bsw + 4096 + o2) = lB;
        st_cluster_u32(pbsw + o1, hA);
        st_cluster_u32(pbsw + o2, hB);
        st_cluster_u32(pbsw + 4096 + o1, lA);
        st_cluster_u32(pbsw + 4096 + o2, lB);
        mbar_arrive_cluster(pefw);
    };

    // ======================= encoder =======================
    auto enc_step = [&](int s, uint32_t eFr, int& fpr, uint32_t bsr, uint32_t bsw,
                        uint32_t pbsw, uint32_t pefw) {
        float xn00 = 0.f, xn01 = 0.f, xn10 = 0.f, xn11 = 0.f;
        if (actc && s + 1 < SS) {
            const float* xb = g_xproj + ((size_t)(s + 1) * BB + (b0 + nb)) * HH;
            xn00 = __ldcs(xb + colg);
            xn01 = __ldcs(xb + (size_t)HH + colg);
            xn10 = __ldcs(xb + colg + 8);
            xn11 = __ldcs(xb + (size_t)HH + colg + 8);
        }
        float sums[4];
        ring_mma(eFr, fpr, bsr, false, sums);
        if (kh) *(float4*)(dsm + partAddr) =
            make_float4(sums[0], sums[1], sums[2], sums[3]);
        __syncthreads();                           // BAR1: partials visible
        if (actc) {
            float4 pp = *(const float4*)(dsm + partPeerA);
            push_state(bsw, pbsw, pefw,
                       tanhfast(sums[0] + pp.x + xc00),
                       tanhfast(sums[1] + pp.y + xc01),
                       tanhfast(sums[2] + pp.z + xc10),
                       tanhfast(sums[3] + pp.w + xc11));
        }
        __syncthreads();                           // BAR2: local half of new slot
        xc00 = xn00; xc01 = xn01; xc10 = xn10; xc11 = xn11;
    };

    #pragma unroll 1
    for (int sb = 0; sb < SS; sb += 4) {
        enc_step(sb + 0, eF[3], fp3, RING(3), RING(0), pRG[0], peF[0]);
        enc_step(sb + 1, eF[0], fp0, RING(0), RING(1), pRG[1], peF[1]);
        enc_step(sb + 2, eF[1], fp1, RING(1), RING(2), pRG[2], peF[2]);
        enc_step(sb + 3, eF[2], fp2, RING(2), RING(3), pRG[3], peF[3]);
    }

    // a_last in slot 3; ALL threads acquire peer half
    mbar_wait_par(eF[3], fp3); fp3 ^= 1;
    if (t < 256) {
        uint32_t w0h = *(const uint32_t*)(dsm + RING(3) + t * 16);
        uint32_t w1h = *(const uint32_t*)(dsm + RING(3) + t * 16 + 4);
        uint32_t w0l = *(const uint32_t*)(dsm + RING(3) + 4096 + t * 16);
        uint32_t w1l = *(const uint32_t*)(dsm + RING(3) + 4096 + t * 16 + 4);
        a4s[t] = make_float4(bfu(w0h) + bfu(w0l), bfu(w0h >> 16) + bfu(w0l >> 16),
                             bfu(w1h) + bfu(w1l), bfu(w1h >> 16) + bfu(w1l >> 16));
    }
    __syncthreads();

    // ======================= glue: y0, base (t<256 compute) =======================
    const int kq = (t >> 5) & 7, cq = lane;
    const int o0    = 2 * (t & 255);
    const int row_o = (o0 >> 2) & 3;
    const int coll  = (o0 >> 4) * 4 + (o0 & 3);
    const int col   = c0 + coll;

    if (t < 256) {
        float acc[16];
        gemv16_g(Wy + (size_t)(kq * 32) * 256 + c0 + cq * 4, &a4s[kq * 32], acc);
        #pragma unroll
        for (int r = 0; r < 4; r++)
            *(float4*)&red[r * RSTRIDE + kq * 128 + cq * 4] =
                make_float4(acc[r * 4], acc[r * 4 + 1], acc[r * 4 + 2], acc[r * 4 + 3]);
    }
    __syncthreads();
    if (t < 256) {
        float2 byv = *(const float2*)&by[col];
        float v0 = 0.f, v1 = 0.f;
        #pragma unroll
        for (int gg = 0; gg < 8; gg++) {
            float2 rv = *(const float2*)&red[row_o * RSTRIDE + gg * 128 + coll];
            v0 += rv.x; v1 += rv.y;
        }
        ((float*)&y4s[col])[row_o]     = sigf(v0 + byv.x);
        ((float*)&y4s[col + 1])[row_o] = sigf(v1 + byv.y);
    }
    __syncthreads();
    if (t < 32) {
        #pragma unroll
        for (int j = 0; j < 4; j++) {
            int idx = c0 + lane + 32 * j;
            st_cluster_f4(py4 + (uint32_t)idx * 16u, y4s[idx]);
        }
    }
    cluster_sync_all();

    if (t < 256) {
        float acc[16];
        gemv16_g(W2x + (size_t)(kq * 32) * 256 + c0 + cq * 4, y4s + kq * 32, acc);
        #pragma unroll
        for (int r = 0; r < 4; r++)
            *(float4*)&red[r * RSTRIDE + kq * 128 + cq * 4] =
                make_float4(acc[r * 4], acc[r * 4 + 1], acc[r * 4 + 2], acc[r * 4 + 3]);
    }
    __syncthreads();
    if (t < 256) {
        float2 b2xv = *(const float2*)&b2x[col];
        float2 b2av = *(const float2*)&b2a[col];
        float v0 = 0.f, v1 = 0.f;
        #pragma unroll
        for (int gg = 0; gg < 8; gg++) {
            float2 rv = *(const float2*)&red[row_o * RSTRIDE + gg * 128 + coll];
            v0 += rv.x; v1 += rv.y;
        }
        basef[row_o * 256 + coll]     = v0 + b2xv.x + b2av.x;
        basef[row_o * 256 + coll + 1] = v1 + b2xv.y + b2av.y;
    }
    __syncthreads();

    // restage A = W2a^T hi/lo, reload register fragments
    {
        const int m = t & 127, hb = t >> 7;
        #pragma unroll 4
        for (int kk = 0; kk < 64; kk++) {
            int k = hb * 64 + kk;
            float v = W2a[(size_t)k * 256 + c0 + m];
            __nv_bfloat16 h = __float2bfloat16(v);
            __nv_bfloat16 l = __float2bfloat16(v - __bfloat162float(h));
            *(unsigned short*)(dsm + m * A_STRIDE + k * 2) = __bfloat16_as_ushort(h);
            *(unsigned short*)(dsm + ALO + m * A_STRIDE + k * 2) = __bfloat16_as_ushort(l);
        }
    }
    __syncthreads();
    load_a_regs();

    const int mbg = mb + g;
    float bbA = 0.f, bbB = 0.f;
    if (actc) {
        bbA = b2x[colg] + b2a[colg];
        bbB = b2x[colg + 8] + b2a[colg + 8];
    }

    // ======================= decoder (ring continues) =======================
    auto dec_step = [&](int i, uint32_t eFr, int& fpr, uint32_t bsr, uint32_t bsw,
                        uint32_t pbsw, uint32_t pefw, bool skipwait) {
        float sums[4];
        ring_mma(eFr, fpr, bsr, skipwait, sums);
        if (kh) *(float4*)(dsm + partAddr) =
            make_float4(sums[0], sums[1], sums[2], sums[3]);
        __syncthreads();
        if (actc) {
            float4 pp = *(const float4*)(dsm + partPeerA);
            float a00, a01, a10, a11;
            if (i == 0) {
                a00 = basef[nb * 256 + mbg];
                a01 = basef[(nb + 1) * 256 + mbg];
                a10 = basef[nb * 256 + mbg + 8];
                a11 = basef[(nb + 1) * 256 + mbg + 8];
            } else {
                a00 = bbA; a01 = bbA; a10 = bbB; a11 = bbB;
            }
            float t00 = tanhfast(sums[0] + pp.x + a00);
            float t01 = tanhfast(sums[1] + pp.y + a01);
            float t10 = tanhfast(sums[2] + pp.z + a10);
            float t11 = tanhfast(sums[3] + pp.w + a11);
            g_ahist[((size_t)(b0 + nb) * LL + i) * 256 + colg]          = t00;
            g_ahist[((size_t)(b0 + nb + 1) * LL + i) * 256 + colg]      = t01;
            g_ahist[((size_t)(b0 + nb) * LL + i) * 256 + colg + 8]      = t10;
            g_ahist[((size_t)(b0 + nb + 1) * LL + i) * 256 + colg + 8]  = t11;
            push_state(bsw, pbsw, pefw, t00, t01, t10, t11);
        }
        __syncthreads();
    };

    #pragma unroll 1
    for (int ib = 0; ib < 16; ib++) {
        const int i0 = ib * 4;
        dec_step(i0 + 0, eF[3], fp3, RING(3), RING(0), pRG[0], peF[0], ib == 0);
        dec_step(i0 + 1, eF[0], fp0, RING(0), RING(1), pRG[1], peF[1], false);
        dec_step(i0 + 2, eF[1], fp1, RING(1), RING(2), pRG[2], peF[2], false);
        dec_step(i0 + 3, eF[2], fp2, RING(2), RING(3), pRG[3], peF[3], false);
    }

    cluster_sync_all();
}

// ---------------------------------------------------------------------------
extern "C" void kernel_launch(void* const* d_in, const int* in_sizes, int n_in,
                              void* d_out, int out_size)
{
    const float* x   = (const float*)d_in[0];
    const float* W1x = (const float*)d_in[1];
    const float* b1x = (const float*)d_in[2];
    const float* W1a = (const float*)d_in[3];
    const float* b1a = (const float*)d_in[4];
    const float* W2x = (const float*)d_in[5];
    const float* b2x = (const float*)d_in[6];
    const float* W2a = (const float*)d_in[7];
    const float* b2a = (const float*)d_in[8];
    const float* Wy  = (const float*)d_in[9];
    const float* by  = (const float*)d_in[10];
    float* out = (float*)d_out;

    (void)in_sizes; (void)n_in; (void)out_size;

    cudaFuncSetAttribute(xproj_mma_kernel,
                         cudaFuncAttributeMaxDynamicSharedMemorySize, XP_SMEM);
    cudaFuncSetAttribute(y_mma_kernel,
                         cudaFuncAttributeMaxDynamicSharedMemorySize, XP_SMEM);
    cudaFuncSetAttribute(rnn_kernel,
                         cudaFuncAttributeMaxDynamicSharedMemorySize, RNN_SMEM);

    wconv_kernel<<<256, 256>>>(W1x);
    wconv_wy_kernel<<<256, 256>>>(Wy);
    dim3 xgrid((BB * SS) / 128, HH / 128);
    xproj_mma_kernel<<<xgrid, 256, XP_SMEM>>>(x, b1x, b1a);
    rnn_kernel<<<BB / 2, NT, RNN_SMEM>>>(W1a, W2x, b2x, W2a, b2a, Wy, by);
    dim3 ygrid((BB * LL) / 128, OO / 128);
    y_mma_kernel<<<ygrid, 256, XP_SMEM>>>(by, out);
}

// round 17
// speedup vs baseline: 1.4223x; 1.4223x over previous
#include <cuda_runtime.h>
#include <cuda_bf16.h>
#include <math.h>
#include <stdint.h>

#define BB 256
#define SS 512
#define II 256
#define HH 256
#define OO 256
#define LL 64

__device__ float g_xproj[(size_t)SS * BB * HH];
__device__ float g_ahist[(size_t)BB * LL * HH];
__device__ int   g_xflag[SS * 4];                  // [s][mblock][nblock]
__device__ __nv_bfloat16 g_wh[256 * 256];          // W1x^T hi [n][k]
__device__ __nv_bfloat16 g_wl[256 * 256];
__device__ __nv_bfloat16 g_wyh[256 * 256];         // Wy^T hi [n][k]
__device__ __nv_bfloat16 g_wyl[256 * 256];

__device__ __forceinline__ float sigf(float x) {
    return __fdividef(1.f, 1.f + __expf(-x));
}
__device__ __forceinline__ float tanhfast(float x) {
    float e = __expf(2.f * x);
    return 1.f - __fdividef(2.f, e + 1.f);
}

__device__ __forceinline__ uint32_t smem_u32(const void* p) {
    uint32_t r;
    asm("{ .reg .u64 t; cvta.to.shared.u64 t, %1; cvt.u32.u64 %0, t; }" : "=r"(r) : "l"(p));
    return r;
}
__device__ __forceinline__ uint32_t mapa_peer(uint32_t a, uint32_t peer) {
    uint32_t r;
    asm("mapa.shared::cluster.u32 %0, %1, %2;" : "=r"(r) : "r"(a), "r"(peer));
    return r;
}
__device__ __forceinline__ void mbar_init(uint32_t a, uint32_t c) {
    asm volatile("mbarrier.init.shared.b64 [%0], %1;" :: "r"(a), "r"(c) : "memory");
}
__device__ __forceinline__ void mbar_arrive_local(uint32_t a) {
    asm volatile("mbarrier.arrive.release.cta.shared::cta.b64 _, [%0];"
                 :: "r"(a) : "memory");
}
__device__ __forceinline__ void mbar_arrive_cluster(uint32_t a) {
    asm volatile("mbarrier.arrive.release.cluster.shared::cluster.b64 _, [%0];"
                 :: "r"(a) : "memory");
}
__device__ __forceinline__ void mbar_wait_par(uint32_t a, uint32_t par) {
    asm volatile(
        "{\n\t.reg .pred P;\n\t"
        "WL%=:\n\t"
        "mbarrier.try_wait.parity.acquire.cluster.shared::cta.b64 P, [%0], %1, 0x989680;\n\t"
        "@P bra WD%=;\n\t"
        "bra WL%=;\n\t"
        "WD%=:\n\t}"
        :: "r"(a), "r"(par) : "memory");
}
__device__ __forceinline__ void st_cluster_f4(uint32_t a, float4 v) {
    asm volatile("st.shared::cluster.v4.b32 [%0], {%1,%2,%3,%4};" :: "r"(a),
                 "r"(__float_as_uint(v.x)), "r"(__float_as_uint(v.y)),
                 "r"(__float_as_uint(v.z)), "r"(__float_as_uint(v.w)) : "memory");
}
__device__ __forceinline__ void st_cluster_u32(uint32_t a, uint32_t v) {
    asm volatile("st.shared::cluster.b32 [%0], %1;" :: "r"(a), "r"(v) : "memory");
}
__device__ __forceinline__ void cluster_sync_all() {
    asm volatile("barrier.cluster.arrive.aligned;" ::: "memory");
    asm volatile("barrier.cluster.wait.aligned;" ::: "memory");
}
__device__ __forceinline__ void ldsm_x4(uint32_t addr, uint32_t r[4]) {
    asm volatile("ldmatrix.sync.aligned.m8n8.x4.shared.b16 {%0,%1,%2,%3}, [%4];"
                 : "=r"(r[0]), "=r"(r[1]), "=r"(r[2]), "=r"(r[3]) : "r"(addr));
}
__device__ __forceinline__ void ldsm_x2t(uint32_t addr, uint32_t& r0, uint32_t& r1) {
    asm volatile("ldmatrix.sync.aligned.m8n8.x2.trans.shared.b16 {%0,%1}, [%2];"
                 : "=r"(r0), "=r"(r1) : "r"(addr));
}
__device__ __forceinline__ void mma_bf16(float c[4], const uint32_t a[4],
                                         uint32_t b0, uint32_t b1) {
    asm volatile(
        "mma.sync.aligned.m16n8k16.row.col.f32.bf16.bf16.f32 "
        "{%0,%1,%2,%3}, {%4,%5,%6,%7}, {%8,%9}, {%0,%1,%2,%3};"
        : "+f"(c[0]), "+f"(c[1]), "+f"(c[2]), "+f"(c[3])
        : "r"(a[0]), "r"(a[1]), "r"(a[2]), "r"(a[3]), "r"(b0), "r"(b1));
}
__device__ __forceinline__ uint32_t packbf2(float a, float b) {
    __nv_bfloat16 ha = __float2bfloat16(a), hb = __float2bfloat16(b);
    return ((uint32_t)__bfloat16_as_ushort(hb) << 16) | __bfloat16_as_ushort(ha);
}
__device__ __forceinline__ float bfu(uint32_t u) {
    return __bfloat162float(__ushort_as_bfloat16((unsigned short)(u & 0xffffu)));
}
__device__ __forceinline__ int ld_acq(const int* p) {
    int v;
    asm volatile("ld.acquire.gpu.global.b32 %0, [%1];" : "=r"(v) : "l"(p) : "memory");
    return v;
}
__device__ __forceinline__ void st_rel(int* p, int v) {
    asm volatile("st.release.gpu.global.b32 [%0], %1;" :: "l"(p), "r"(v) : "memory");
}

// ===========================================================================
// Kernel 0a/0b: weight conversions; 0a also zeroes the xproj flags.
// ===========================================================================
__global__ void wconv_kernel(const float* __restrict__ W1x)
{
    int k = blockIdx.x, n = threadIdx.x;
    if (blockIdx.x < 8) g_xflag[blockIdx.x * 256 + threadIdx.x] = 0;
    float v = W1x[k * 256 + n];
    __nv_bfloat16 h = __float2bfloat16(v);
    __nv_bfloat16 l = __float2bfloat16(v - __bfloat162float(h));
    g_wh[n * 256 + k] = h;
    g_wl[n * 256 + k] = l;
}
__global__ void wconv_wy_kernel(const float* __restrict__ Wy)
{
    int k = blockIdx.x, n = threadIdx.x;
    float v = Wy[k * 256 + n];
    __nv_bfloat16 h = __float2bfloat16(v);
    __nv_bfloat16 l = __float2bfloat16(v - __bfloat162float(h));
    g_wyh[n * 256 + k] = h;
    g_wyl[n * 256 + k] = l;
}

// ===========================================================================
// GEMM pieces (R8-proven)
// ===========================================================================
#define SB_BH    0
#define SB_BL    65536
#define SB_A     131072
#define SB_BIAS  196608
#define XP_SMEM  197120

__device__ __forceinline__ void afragx(uint32_t Ab, int mbase, int j, int lane,
                                       uint32_t r[4]) {
    int row = mbase + (lane & 15);
    int q   = j * 2 + (lane >> 4);
    uint32_t addr = Ab + (uint32_t)(row * 128 + ((q ^ row) & 7) * 16);
    ldsm_x4(addr, r);
}
__device__ __forceinline__ void bfragx(uint32_t Bb, int nbase, int ks, int lane,
                                       uint32_t r[4]) {
    int row = nbase + (lane & 7) + ((lane >> 4) << 3);
    int q   = ks * 2 + ((lane >> 3) & 1);
    uint32_t qp = (uint32_t)((q & ~7) | ((q ^ row) & 7));
    uint32_t addr = Bb + (uint32_t)(row * 512) + qp * 16;
    ldsm_x4(addr, r);
}

__device__ __forceinline__ void load_a_rows(unsigned char* sm, int p,
                                            const float* __restrict__ Arows,
                                            int c, int t)
{
    const int r = t >> 1, hf = t & 1, rx = r & 7;
    unsigned char* ah = sm + SB_A + p * 32768;
    unsigned char* al = ah + 16384;
    const float* xr = Arows + (size_t)r * 256 + c * 64 + hf * 32;
    #pragma unroll
    for (int jj = 0; jj < 4; jj++) {
        float4 v0 = *(const float4*)(xr + jj * 8);
        float4 v1 = *(const float4*)(xr + jj * 8 + 4);
        uint4 h, l;
        h.x = packbf2(v0.x, v0.y); h.y = packbf2(v0.z, v0.w);
        h.z = packbf2(v1.x, v1.y); h.w = packbf2(v1.z, v1.w);
        l.x = packbf2(v0.x - bfu(h.x), v0.y - bfu(h.x >> 16));
        l.y = packbf2(v0.z - bfu(h.y), v0.w - bfu(h.y >> 16));
        l.z = packbf2(v1.x - bfu(h.z), v1.y - bfu(h.z >> 16));
        l.w = packbf2(v1.z - bfu(h.w), v1.w - bfu(h.w >> 16));
        int q = hf * 4 + jj;
        uint32_t off = (uint32_t)(r * 128 + (q ^ rx) * 16);
        *(uint4*)(ah + off) = h;
        *(uint4*)(al + off) = l;
    }
}

// D[128x128] tile, 3-term hi/lo. MODE 0: +bias -> g_xproj. MODE 1: sigmoid -> out.
template <int MODE>
__device__ void gemm128(const float* __restrict__ Arows, int m0,
                        const __nv_bfloat16* __restrict__ Wth,
                        const __nv_bfloat16* __restrict__ Wtl,
                        const float* __restrict__ bias1,
                        const float* __restrict__ bias2,
                        int n0, float* __restrict__ outp,
                        const float* __restrict__ xsrc, int b0x, int sx)
{
    extern __shared__ __align__(1024) unsigned char sm[];
    const int t = threadIdx.x;
    const int wid = t >> 5, lane = t & 31;
    const uint32_t smb = smem_u32(sm);
    const int mw = (wid & 1) * 64;
    const int nw = (wid >> 1) * 32;

    #pragma unroll 4
    for (int i = 0; i < 16; i++) {
        int idx = i * 256 + t;
        int rr = idx >> 5, q = idx & 31;
        uint32_t qp = (uint32_t)((q & ~7) | ((q ^ rr) & 7));
        size_t src = (size_t)(n0 + rr) * 256 + q * 8;
        *(uint4*)(sm + SB_BH + rr * 512 + qp * 16) = *(const uint4*)(Wth + src);
        *(uint4*)(sm + SB_BL + rr * 512 + qp * 16) = *(const uint4*)(Wtl + src);
    }
    if (t < 128) {
        float b = bias1[n0 + t];
        if (bias2) b += bias2[n0 + t];
        ((float*)(sm + SB_BIAS))[t] = b;
    }

    auto load_chunk = [&](int p, int c) {
        if (MODE == 0) {
            // A rows from x[(b0x+r)*SS + sx][...]
            const int r = t >> 1, hf = t & 1, rx = r & 7;
            unsigned char* ah = sm + SB_A + p * 32768;
            unsigned char* al = ah + 16384;
            const float* xr = xsrc + ((size_t)(b0x + r) * SS + sx) * II + c * 64 + hf * 32;
            #pragma unroll
            for (int jj = 0; jj < 4; jj++) {
                float4 v0 = *(const float4*)(xr + jj * 8);
                float4 v1 = *(const float4*)(xr + jj * 8 + 4);
                uint4 h, l;
                h.x = packbf2(v0.x, v0.y); h.y = packbf2(v0.z, v0.w);
                h.z = packbf2(v1.x, v1.y); h.w = packbf2(v1.z, v1.w);
                l.x = packbf2(v0.x - bfu(h.x), v0.y - bfu(h.x >> 16));
                l.y = packbf2(v0.z - bfu(h.y), v0.w - bfu(h.y >> 16));
                l.z = packbf2(v1.x - bfu(h.z), v1.y - bfu(h.z >> 16));
                l.w = packbf2(v1.z - bfu(h.w), v1.w - bfu(h.w >> 16));
                int q = hf * 4 + jj;
                uint32_t off = (uint32_t)(r * 128 + (q ^ rx) * 16);
                *(uint4*)(ah + off) = h;
                *(uint4*)(al + off) = l;
            }
        } else {
            load_a_rows(sm, p, Arows, c, t);
        }
    };

    load_chunk(0, 0);
    __syncthreads();

    float acc[4][4][4];
    #pragma unroll
    for (int mt = 0; mt < 4; mt++)
        #pragma unroll
        for (int nt = 0; nt < 4; nt++)
            #pragma unroll
            for (int e = 0; e < 4; e++) acc[mt][nt][e] = 0.f;

    const uint32_t Bh = smb + SB_BH, Bl = smb + SB_BL;

    #pragma unroll 1
    for (int c = 0; c < 4; c++) {
        const int p = c & 1;
        if (c < 3) load_chunk(1 - p, c + 1);
        const uint32_t Abh = smb + SB_A + p * 32768;
        const uint32_t Abl = Abh + 16384;
        #pragma unroll
        for (int j = 0; j < 4; j++) {
            const int ks = c * 4 + j;
            uint32_t bh[8], bl[8];
            bfragx(Bh, nw,      ks, lane, bh);
            bfragx(Bh, nw + 16, ks, lane, bh + 4);
            bfragx(Bl, nw,      ks, lane, bl);
            bfragx(Bl, nw + 16, ks, lane, bl + 4);
            #pragma unroll
            for (int mt = 0; mt < 4; mt++) {
                uint32_t ah[4], al[4];
                afragx(Abh, mw + mt * 16, j, lane, ah);
                afragx(Abl, mw + mt * 16, j, lane, al);
                #pragma unroll
                for (int nt = 0; nt < 4; nt++) {
                    mma_bf16(acc[mt][nt], ah, bh[nt * 2], bh[nt * 2 + 1]);
                    mma_bf16(acc[mt][nt], ah, bl[nt * 2], bl[nt * 2 + 1]);
                    mma_bf16(acc[mt][nt], al, bh[nt * 2], bh[nt * 2 + 1]);
                }
            }
        }
        __syncthreads();
    }

    const int g = lane >> 2, tig = lane & 3;
    const float* bias_sm = (const float*)(sm + SB_BIAS);
    #pragma unroll
    for (int mt = 0; mt < 4; mt++) {
        const int mrow = m0 + mw + mt * 16 + g;
        #pragma unroll
        for (int nt = 0; nt < 4; nt++) {
            const int nl = nw + nt * 8 + tig * 2;
            const float bz0 = bias_sm[nl], bz1 = bias_sm[nl + 1];
            float2 v0, v1;
            if (MODE == 0) {
                v0 = make_float2(acc[mt][nt][0] + bz0, acc[mt][nt][1] + bz1);
                v1 = make_float2(acc[mt][nt][2] + bz0, acc[mt][nt][3] + bz1);
            } else {
                v0 = make_float2(sigf(acc[mt][nt][0] + bz0), sigf(acc[mt][nt][1] + bz1));
                v1 = make_float2(sigf(acc[mt][nt][2] + bz0), sigf(acc[mt][nt][3] + bz1));
            }
            *(float2*)&outp[(size_t)mrow * 256 + n0 + nl] = v0;
            *(float2*)&outp[(size_t)(mrow + 8) * 256 + n0 + nl] = v1;
        }
    }
}

__global__ __launch_bounds__(256, 1) void y_mma_kernel(
    const float* __restrict__ by, float* __restrict__ out)
{
    gemm128<1>(g_ahist + (size_t)blockIdx.x * 128 * 256, blockIdx.x * 128,
               g_wyh, g_wyl, by, nullptr, blockIdx.y * 128, out, nullptr, 0, 0);
}

// ===========================================================================
// Fused kernel: blocks 0..63 = RNN clusters (8 batch rows each);
//               blocks 64..147 = xproj tile workers (flag-published).
// ===========================================================================
#define A_STRIDE 528
#define ALO      67584
#define RING(i)  (135168 + (i) * 8192)
#define A4OFF    196608
#define Y4OFF    204800
#define REDOFF   208896
#define MBOFF    225408
#define RNN_SMEM 229568
#define GRSTRIDE 1024

__device__ __forceinline__ void gemv16_g(const float* __restrict__ Wp,
                                         const float4* __restrict__ a, float acc[16])
{
    #pragma unroll
    for (int j = 0; j < 16; j++) acc[j] = 0.f;
    #pragma unroll 16
    for (int k = 0; k < 32; k++) {
        float4 w  = *(const float4*)(Wp + (size_t)k * 256);
        float4 av = a[k];
        acc[0]  = fmaf(av.x, w.x, acc[0]);  acc[1]  = fmaf(av.x, w.y, acc[1]);
        acc[2]  = fmaf(av.x, w.z, acc[2]);  acc[3]  = fmaf(av.x, w.w, acc[3]);
        acc[4]  = fmaf(av.y, w.x, acc[4]);  acc[5]  = fmaf(av.y, w.y, acc[5]);
        acc[6]  = fmaf(av.y, w.z, acc[6]);  acc[7]  = fmaf(av.y, w.w, acc[7]);
        acc[8]  = fmaf(av.z, w.x, acc[8]);  acc[9]  = fmaf(av.z, w.y, acc[9]);
        acc[10] = fmaf(av.z, w.z, acc[10]); acc[11] = fmaf(av.z, w.w, acc[11]);
        acc[12] = fmaf(av.w, w.x, acc[12]); acc[13] = fmaf(av.w, w.y, acc[13]);
        acc[14] = fmaf(av.w, w.z, acc[14]); acc[15] = fmaf(av.w, w.w, acc[15]);
    }
}

__global__ __launch_bounds__(256, 1) __cluster_dims__(2, 1, 1)
void rnn_kernel(const float* __restrict__ x,
                const float* __restrict__ b1x, const float* __restrict__ b1a,
                const float* __restrict__ W1a,
                const float* __restrict__ W2x, const float* __restrict__ b2x,
                const float* __restrict__ W2a, const float* __restrict__ b2a,
                const float* __restrict__ Wy,  const float* __restrict__ by)
{
    // ---------------- worker role ----------------
    if (blockIdx.x >= 64) {
        const int wblk = (int)blockIdx.x - 64;
        for (int tid = wblk; tid < 2048; tid += 84) {
            const int s = tid >> 2, mb = (tid >> 1) & 1, nbk = tid & 1;
            gemm128<0>(nullptr, s * 256 + mb * 128, g_wh, g_wl, b1x, b1a,
                       nbk * 128, g_xproj, x, mb * 128, s);
            __syncthreads();
            if (threadIdx.x == 0) st_rel(&g_xflag[tid], 1);
        }
        return;
    }

    // ---------------- rnn role ----------------
    extern __shared__ __align__(16) unsigned char dsm[];
    float4* a4s   = (float4*)(dsm + A4OFF);        // [2][256] (rows 0-3, 4-7)
    float*  basef = (float*)(dsm + REDOFF);        // [8][256]
    unsigned long long* mbars = (unsigned long long*)(dsm + MBOFF);

    const int t    = threadIdx.x;
    const int lane = t & 31;
    const int wid  = t >> 5;
    uint32_t rank;
    asm("mov.u32 %0, %%cluster_ctarank;" : "=r"(rank));
    const uint32_t peer = rank ^ 1;
    const int b0 = (blockIdx.x >> 1) * 8;
    const int c0 = (int)rank * 128;
    const uint32_t smb = smem_u32(dsm);
    const int mbf = b0 >> 7;

    const int mb   = wid * 16;
    const int g    = lane >> 2;
    const int tig  = lane & 3;
    const int colg = c0 + mb + g;
    const int nb   = 2 * tig;                      // batch 0..7
    const uint32_t aAddrBase = smb + (uint32_t)((mb + (lane & 15)) * A_STRIDE)
                             + (uint32_t)((lane >> 4) * 16);

    uint32_t eF[4], peF[4], pRG[4];
    #pragma unroll
    for (int i = 0; i < 4; i++) {
        eF[i]  = smem_u32(&mbars[i]);
        peF[i] = mapa_peer(eF[i], peer);
        pRG[i] = mapa_peer(smb + (uint32_t)RING(i), peer);
    }
    uint32_t py4 = mapa_peer(smb + (uint32_t)RING(0), peer);

    if (t == 0) {
        mbar_init(eF[0], 256); mbar_init(eF[1], 256);
        mbar_init(eF[2], 256); mbar_init(eF[3], 256);
    }
    // zero ring slot 3 (initial state 0) — 8 KB / 256 thr
    *(uint4*)(dsm + RING(3) + t * 16) = make_uint4(0, 0, 0, 0);
    *(uint4*)(dsm + RING(3) + (t + 256) * 16) = make_uint4(0, 0, 0, 0);
    // stage A = W1a^T hi/lo
    {
        const int m = t & 127, hb = t >> 7;
        #pragma unroll 4
        for (int kk = 0; kk < 128; kk++) {
            int k = hb * 128 + kk;
            float v = W1a[(size_t)k * 256 + c0 + m];
            __nv_bfloat16 h = __float2bfloat16(v);
            __nv_bfloat16 l = __float2bfloat16(v - __bfloat162float(h));
            *(unsigned short*)(dsm + m * A_STRIDE + k * 2) = __bfloat16_as_ushort(h);
            *(unsigned short*)(dsm + ALO + m * A_STRIDE + k * 2) = __bfloat16_as_ushort(l);
        }
    }
    __syncthreads();

    uint32_t ah_r[64], al_r[64];
    auto load_a_regs = [&]() {
        #pragma unroll
        for (int j = 0; j < 8; j++) {
            uint32_t aa = aAddrBase + (uint32_t)((c0 + j * 16) * 2);
            ldsm_x4(aa, &ah_r[j * 4]);
            ldsm_x4(aa + ALO, &al_r[j * 4]);
        }
        #pragma unroll
        for (int j = 0; j < 8; j++) {
            uint32_t aa = aAddrBase + (uint32_t)(((c0 ^ 128) + j * 16) * 2);
            ldsm_x4(aa, &ah_r[(8 + j) * 4]);
            ldsm_x4(aa + ALO, &al_r[(8 + j) * 4]);
        }
    };
    load_a_regs();

    cluster_sync_all();
    mbar_arrive_local(eF[3]);                      // prime slot 3 (256 arrives)

    // xc prefetch for s=0 (flag-gated)
    float xc00, xc01, xc10, xc11;
    {
        const int* fp = &g_xflag[0 * 4 + mbf * 2 + (int)rank];
        while (!ld_acq(fp)) {}
        const float* xb = g_xproj + (size_t)(b0 + nb) * HH;
        xc00 = __ldcs(xb + colg);
        xc01 = __ldcs(xb + (size_t)HH + colg);
        xc10 = __ldcs(xb + colg + 8);
        xc11 = __ldcs(xb + (size_t)HH + colg + 8);
    }

    int fp0 = 0, fp1 = 0, fp2 = 0, fp3 = 0;

    auto ring_mma = [&](uint32_t eFr, int& fpr, uint32_t bsr, bool skipwait,
                        float sums[4]) {
        float acc[6][4];
        #pragma unroll
        for (int i = 0; i < 6; i++)
            #pragma unroll
            for (int e = 0; e < 4; e++) acc[i][e] = 0.f;
        const uint32_t Bsr = smb + bsr;
        #pragma unroll
        for (int j = 0; j < 8; j++) {
            const int k0 = c0 + j * 16;
            uint32_t bh0, bh1, bl0, bl1;
            uint32_t ba = Bsr + (uint32_t)((k0 + (lane & 15)) * 16);
            ldsm_x2t(ba, bh0, bh1);
            ldsm_x2t(ba + 4096, bl0, bl1);
            const int sel = j & 1;
            mma_bf16(acc[sel],     &ah_r[j * 4], bh0, bh1);
            mma_bf16(acc[2 + sel], &ah_r[j * 4], bl0, bl1);
            mma_bf16(acc[4 + sel], &al_r[j * 4], bh0, bh1);
        }
        if (!skipwait) { mbar_wait_par(eFr, fpr); fpr ^= 1; }
        #pragma unroll
        for (int j = 0; j < 8; j++) {
            const int k0 = (c0 ^ 128) + j * 16;
            uint32_t bh0, bh1, bl0, bl1;
            uint32_t ba = Bsr + (uint32_t)((k0 + (lane & 15)) * 16);
            ldsm_x2t(ba, bh0, bh1);
            ldsm_x2t(ba + 4096, bl0, bl1);
            const int sel = j & 1;
            mma_bf16(acc[sel],     &ah_r[(8 + j) * 4], bh0, bh1);
            mma_bf16(acc[2 + sel], &ah_r[(8 + j) * 4], bl0, bl1);
            mma_bf16(acc[4 + sel], &al_r[(8 + j) * 4], bh0, bh1);
        }
        #pragma unroll
        for (int e = 0; e < 4; e++)
            sums[e] = acc[0][e] + acc[1][e] + acc[2][e] + acc[3][e]
                    + acc[4][e] + acc[5][e];
    };

    auto push_state = [&](uint32_t bsw, uint32_t pbsw, uint32_t pefw,
                          float t00, float t01, float t10, float t11) {
        uint32_t hA = packbf2(t00, t01);
        uint32_t hB = packbf2(t10, t11);
        uint32_t lA = packbf2(t00 - bfu(hA), t01 - bfu(hA >> 16));
        uint32_t lB = packbf2(t10 - bfu(hB), t11 - bfu(hB >> 16));
        const uint32_t o1 = (uint32_t)(colg * 16 + tig * 4);
        const uint32_t o2 = (uint32_t)((colg + 8) * 16 + tig * 4);
        *(uint32_t*)(dsm + bsw + o1) = hA;
        *(uint32_t*)(dsm + bsw + o2) = hB;
        *(uint32_t*)(dsm + bsw + 4096 + o1) = lA;
        *(uint32_t*)(dsm + bsw + 4096 + o2) = lB;
        st_cluster_u32(pbsw + o1, hA);
        st_cluster_u32(pbsw + o2, hB);
        st_cluster_u32(pbsw + 4096 + o1, lA);
        st_cluster_u32(pbsw + 4096 + o2, lB);
        mbar_arrive_cluster(pefw);
    };

    // ======================= encoder =======================
    auto enc_step = [&](int s, uint32_t eFr, int& fpr, uint32_t bsr, uint32_t bsw,
                        uint32_t pbsw, uint32_t pefw) {
        const int sn = s + 1;
        int flr = 1;
        const int* fp = &g_xflag[sn * 4 + mbf * 2 + (int)rank];
        if (sn < SS) flr = ld_acq(fp);             // early hint (acquire)

        float sums[4];
        ring_mma(eFr, fpr, bsr, false, sums);

        float xn00 = 0.f, xn01 = 0.f, xn10 = 0.f, xn11 = 0.f;
        if (sn < SS) {
            if (!flr) { do { flr = ld_acq(fp); } while (!flr); }
            const float* xb = g_xproj + ((size_t)sn * BB + (b0 + nb)) * HH;
            xn00 = __ldcs(xb + colg);
            xn01 = __ldcs(xb + (size_t)HH + colg);
            xn10 = __ldcs(xb + colg + 8);
            xn11 = __ldcs(xb + (size_t)HH + colg + 8);
        }
        push_state(bsw, pbsw, pefw,
                   tanhfast(sums[0] + xc00), tanhfast(sums[1] + xc01),
                   tanhfast(sums[2] + xc10), tanhfast(sums[3] + xc11));
        __syncthreads();
        xc00 = xn00; xc01 = xn01; xc10 = xn10; xc11 = xn11;
    };

    #pragma unroll 1
    for (int sb = 0; sb < SS; sb += 4) {
        enc_step(sb + 0, eF[3], fp3, RING(3), RING(0), pRG[0], peF[0]);
        enc_step(sb + 1, eF[0], fp0, RING(0), RING(1), pRG[1], peF[1]);
        enc_step(sb + 2, eF[1], fp1, RING(1), RING(2), pRG[2], peF[2]);
        enc_step(sb + 3, eF[2], fp2, RING(2), RING(3), pRG[3], peF[3]);
    }

    // a_last in slot 3 (PRESERVE slot 3: decoder step 0 reads it)
    mbar_wait_par(eF[3], fp3); fp3 ^= 1;
    {
        uint4 hi = *(const uint4*)(dsm + RING(3) + t * 16);
        uint4 lo = *(const uint4*)(dsm + RING(3) + 4096 + t * 16);
        a4s[t] = make_float4(bfu(hi.x) + bfu(lo.x), bfu(hi.x >> 16) + bfu(lo.x >> 16),
                             bfu(hi.y) + bfu(lo.y), bfu(hi.y >> 16) + bfu(lo.y >> 16));
        a4s[256 + t] = make_float4(bfu(hi.z) + bfu(lo.z), bfu(hi.z >> 16) + bfu(lo.z >> 16),
                                   bfu(hi.w) + bfu(lo.w), bfu(hi.w >> 16) + bfu(lo.w >> 16));
    }
    __syncthreads();

    // ======================= glue (scratch in ring slots 0-2) =======================
    float4* y4s  = (float4*)(dsm + RING(0));       // [2][256]
    float*  gred = (float*)(dsm + RING(1));        // 16 KB (slots 1,2)
    const int kq = wid, cq = lane;
    const int o0    = 2 * t;
    const int row_o = (o0 >> 2) & 3;
    const int coll  = (o0 >> 4) * 4 + (o0 & 3);
    const int col   = c0 + coll;

    {
        float2 byv = *(const float2*)&by[col];
        #pragma unroll 1
        for (int h = 0; h < 2; h++) {
            float acc[16];
            gemv16_g(Wy + (size_t)(kq * 32) * 256 + c0 + cq * 4,
                     &a4s[h * 256 + kq * 32], acc);
            #pragma unroll
            for (int r = 0; r < 4; r++)
                *(float4*)&gred[r * GRSTRIDE + kq * 128 + cq * 4] =
                    make_float4(acc[r * 4], acc[r * 4 + 1], acc[r * 4 + 2], acc[r * 4 + 3]);
            __syncthreads();
            float v0 = 0.f, v1 = 0.f;
            #pragma unroll
            for (int gg = 0; gg < 8; gg++) {
                float2 rv = *(const float2*)&gred[row_o * GRSTRIDE + gg * 128 + coll];
                v0 += rv.x; v1 += rv.y;
            }
            ((float*)&y4s[h * 256 + col])[row_o]     = sigf(v0 + byv.x);
            ((float*)&y4s[h * 256 + col + 1])[row_o] = sigf(v1 + byv.y);
            __syncthreads();
        }
        // push y0 (both halves) to peer
        if (t < 128) {
            #pragma unroll
            for (int h = 0; h < 2; h++) {
                int idx = h * 256 + c0 + t;
                st_cluster_f4(py4 + (uint32_t)idx * 16u, y4s[idx]);
            }
        }
        cluster_sync_all();

        float2 b2xv = *(const float2*)&b2x[col];
        float2 b2av = *(const float2*)&b2a[col];
        float bb0 = b2xv.x + b2av.x, bb1 = b2xv.y + b2av.y;
        #pragma unroll 1
        for (int h = 0; h < 2; h++) {
            float acc[16];
            gemv16_g(W2x + (size_t)(kq * 32) * 256 + c0 + cq * 4,
                     &y4s[h * 256 + kq * 32], acc);
            #pragma unroll
            for (int r = 0; r < 4; r++)
                *(float4*)&gred[r * GRSTRIDE + kq * 128 + cq * 4] =
                    make_float4(acc[r * 4], acc[r * 4 + 1], acc[r * 4 + 2], acc[r * 4 + 3]);
            __syncthreads();
            float v0 = 0.f, v1 = 0.f;
            #pragma unroll
            for (int gg = 0; gg < 8; gg++) {
                float2 rv = *(const float2*)&gred[row_o * GRSTRIDE + gg * 128 + coll];
                v0 += rv.x; v1 += rv.y;
            }
            basef[(h * 4 + row_o) * 256 + coll]     = v0 + bb0;
            basef[(h * 4 + row_o) * 256 + coll + 1] = v1 + bb1;
            __syncthreads();
        }
    }

    // restage A = W2a^T hi/lo, reload register fragments
    {
        const int m = t & 127, hb = t >> 7;
        #pragma unroll 4
        for (int kk = 0; kk < 128; kk++) {
            int k = hb * 128 + kk;
            float v = W2a[(size_t)k * 256 + c0 + m];
            __nv_bfloat16 h = __float2bfloat16(v);
            __nv_bfloat16 l = __float2bfloat16(v - __bfloat162float(h));
            *(unsigned short*)(dsm + m * A_STRIDE + k * 2) = __bfloat16_as_ushort(h);
            *(unsigned short*)(dsm + ALO + m * A_STRIDE + k * 2) = __bfloat16_as_ushort(l);
        }
    }
    __syncthreads();
    load_a_regs();

    const int mbg = mb + g;
    const float bbA = b2x[colg] + b2a[colg];
    const float bbB = b2x[colg + 8] + b2a[colg + 8];

    // ======================= decoder (ring continues) =======================
    auto dec_step = [&](int i, uint32_t eFr, int& fpr, uint32_t bsr, uint32_t bsw,
                        uint32_t pbsw, uint32_t pefw, bool skipwait) {
        float sums[4];
        ring_mma(eFr, fpr, bsr, skipwait, sums);
        float a00, a01, a10, a11;
        if (i == 0) {
            a00 = basef[nb * 256 + mbg];
            a01 = basef[(nb + 1) * 256 + mbg];
            a10 = basef[nb * 256 + mbg + 8];
            a11 = basef[(nb + 1) * 256 + mbg + 8];
        } else {
            a00 = bbA; a01 = bbA; a10 = bbB; a11 = bbB;
        }
        float t00 = tanhfast(sums[0] + a00);
        float t01 = tanhfast(sums[1] + a01);
        float t10 = tanhfast(sums[2] + a10);
        float t11 = tanhfast(sums[3] + a11);
        g_ahist[((size_t)(b0 + nb) * LL + i) * 256 + colg]          = t00;
        g_ahist[((size_t)(b0 + nb + 1) * LL + i) * 256 + colg]      = t01;
        g_ahist[((size_t)(b0 + nb) * LL + i) * 256 + colg + 8]      = t10;
        g_ahist[((size_t)(b0 + nb + 1) * LL + i) * 256 + colg + 8]  = t11;
        push_state(bsw, pbsw, pefw, t00, t01, t10, t11);
        __syncthreads();
    };

    #pragma unroll 1
    for (int ib = 0; ib < 16; ib++) {
        const int i0 = ib * 4;
        dec_step(i0 + 0, eF[3], fp3, RING(3), RING(0), pRG[0], peF[0], ib == 0);
        dec_step(i0 + 1, eF[0], fp0, RING(0), RING(1), pRG[1], peF[1], false);
        dec_step(i0 + 2, eF[1], fp1, RING(1), RING(2), pRG[2], peF[2], false);
        dec_step(i0 + 3, eF[2], fp2, RING(2), RING(3), pRG[3], peF[3], false);
    }

    cluster_sync_all();
}

// ---------------------------------------------------------------------------
extern "C" void kernel_launch(void* const* d_in, const int* in_sizes, int n_in,
                              void* d_out, int out_size)
{
    const float* x   = (const float*)d_in[0];
    const float* W1x = (const float*)d_in[1];
    const float* b1x = (const float*)d_in[2];
    const float* W1a = (const float*)d_in[3];
    const float* b1a = (const float*)d_in[4];
    const float* W2x = (const float*)d_in[5];
    const float* b2x = (const float*)d_in[6];
    const float* W2a = (const float*)d_in[7];
    const float* b2a = (const float*)d_in[8];
    const float* Wy  = (const float*)d_in[9];
    const float* by  = (const float*)d_in[10];
    float* out = (float*)d_out;

    (void)in_sizes; (void)n_in; (void)out_size;

    cudaFuncSetAttribute(y_mma_kernel,
                         cudaFuncAttributeMaxDynamicSharedMemorySize, XP_SMEM);
    cudaFuncSetAttribute(rnn_kernel,
                         cudaFuncAttributeMaxDynamicSharedMemorySize, RNN_SMEM);

    wconv_kernel<<<256, 256>>>(W1x);
    wconv_wy_kernel<<<256, 256>>>(Wy);
    rnn_kernel<<<148, 256, RNN_SMEM>>>(x, b1x, b1a, W1a, W2x, b2x, W2a, b2a, Wy, by);
    dim3 ygrid((BB * LL) / 128, OO / 128);
    y_mma_kernel<<<ygrid, 256, XP_SMEM>>>(by, out);
}